// round 2
// baseline (speedup 1.0000x reference)
#include <cuda_runtime.h>

// ----------------------------------------------------------------------------
// ScaledDotProduct: out = sigmoid((q Wq^T + bq)(k Wk^T + bk)^T / sqrt(256)) (v Wv^T + bv)
// B=4, S=4096, DIM=1024, QK_DIM=256.
//
// Strategy (round 0 baseline, tensor-core tf32 via mma.sync):
//   1) qp = q @ Wq^T + bq           [16384 x 256]   (GEMM, B as [N,K])
//   2) kp = k @ Wk^T + bk           [16384 x 256]
//   3) vp = v @ Wv^T + bv           [16384 x 1024]
//   4) z  = sigmoid(qp kp^T / 16)   [4 x 4096 x 4096]  (batched GEMM, fused epilogue)
//   5) out = z @ vp                 [4 x 4096 x 1024]  (batched GEMM, B as [K,N])
// Scratch lives in __device__ globals (no allocations anywhere).
// tf32 rounding (cvt.rna) applied at smem-store time.
// ----------------------------------------------------------------------------

#define BM 128
#define BN 64
#define BK 32
#define LDA_S 36   // BK + 4 pad  -> A-fragment LDS conflict-free
#define LDB_S 72   // BN + 8 pad  -> B-fragment LDS conflict-free

__device__ float g_qp[(size_t)4 * 4096 * 256];
__device__ float g_kp[(size_t)4 * 4096 * 256];
__device__ float g_vp[(size_t)4 * 4096 * 1024];
__device__ float g_z [(size_t)4 * 4096 * 4096];

__device__ __forceinline__ unsigned int f2tf(float x) {
    unsigned int r;
    asm("cvt.rna.tf32.f32 %0, %1;" : "=r"(r) : "f"(x));
    return r;
}

__device__ __forceinline__ void mma8(float* c, const unsigned int* a, const unsigned int* b) {
    asm volatile(
        "mma.sync.aligned.m16n8k8.row.col.f32.tf32.tf32.f32 "
        "{%0,%1,%2,%3}, {%4,%5,%6,%7}, {%8,%9}, {%0,%1,%2,%3};\n"
        : "+f"(c[0]), "+f"(c[1]), "+f"(c[2]), "+f"(c[3])
        : "r"(a[0]), "r"(a[1]), "r"(a[2]), "r"(a[3]),
          "r"(b[0]), "r"(b[1]));
}

// MODE_B: 0 -> B is [N,K] row-major (we compute A @ B^T)
//         1 -> B is [K,N] row-major (we compute A @ B)
// EPI:    0 -> none, 1 -> +bias[n], 2 -> sigmoid(x/16)
template <int MODE_B, int EPI>
__global__ __launch_bounds__(256, 2)
void gemm_tf32(const float* __restrict__ A, const float* __restrict__ B,
               const float* __restrict__ bias, float* __restrict__ C,
               int N, int K,
               size_t sA, size_t sB, size_t sC)
{
    __shared__ unsigned int As[BM * LDA_S];
    __shared__ unsigned int Bs[BK * LDB_S];

    const float* Ab = A + (size_t)blockIdx.z * sA;
    const float* Bb = B + (size_t)blockIdx.z * sB;
    float*       Cb = C + (size_t)blockIdx.z * sC;

    const int bMr  = blockIdx.x * BM;
    const int bNc  = blockIdx.y * BN;
    const int tid  = threadIdx.x;
    const int lane = tid & 31;
    const int warp = tid >> 5;
    const int wm   = (warp >> 1) * 32;  // 4 warps along M (32 rows each)
    const int wn   = (warp & 1) * 32;   // 2 warps along N (32 cols each)

    float acc[2][4][4];
#pragma unroll
    for (int i = 0; i < 2; i++)
#pragma unroll
        for (int j = 0; j < 4; j++)
#pragma unroll
            for (int t = 0; t < 4; t++) acc[i][j][t] = 0.0f;

    for (int k0 = 0; k0 < K; k0 += BK) {
        __syncthreads();

        // ---- stage A tile [BM x BK] (row-major along K, contiguous loads) ----
#pragma unroll
        for (int it = 0; it < 4; it++) {
            int f4 = tid + it * 256;          // 1024 float4 total
            int r  = f4 >> 3;                 // 8 float4 per row
            int cc = (f4 & 7) << 2;
            float4 v = *reinterpret_cast<const float4*>(
                Ab + (size_t)(bMr + r) * K + (k0 + cc));
            *reinterpret_cast<uint4*>(&As[r * LDA_S + cc]) =
                make_uint4(f2tf(v.x), f2tf(v.y), f2tf(v.z), f2tf(v.w));
        }

        // ---- stage B tile into Bs[k][n] ----
        if (MODE_B == 0) {
#pragma unroll
            for (int it = 0; it < 2; it++) {
                int f4 = tid + it * 256;      // 512 float4 total
                int n  = f4 >> 3;             // 8 float4 per B row (length BK)
                int kk = (f4 & 7) << 2;
                float4 v = *reinterpret_cast<const float4*>(
                    Bb + (size_t)(bNc + n) * K + (k0 + kk));
                Bs[(kk + 0) * LDB_S + n] = f2tf(v.x);
                Bs[(kk + 1) * LDB_S + n] = f2tf(v.y);
                Bs[(kk + 2) * LDB_S + n] = f2tf(v.z);
                Bs[(kk + 3) * LDB_S + n] = f2tf(v.w);
            }
        } else {
#pragma unroll
            for (int it = 0; it < 2; it++) {
                int f4 = tid + it * 256;
                int r  = f4 >> 4;             // 16 float4 per row of BN=64
                int cc = (f4 & 15) << 2;
                float4 v = *reinterpret_cast<const float4*>(
                    Bb + (size_t)(k0 + r) * N + (bNc + cc));
                *reinterpret_cast<uint4*>(&Bs[r * LDB_S + cc]) =
                    make_uint4(f2tf(v.x), f2tf(v.y), f2tf(v.z), f2tf(v.w));
            }
        }

        __syncthreads();

        // ---- compute: 4 k-steps of m16n8k8 ----
#pragma unroll
        for (int ks = 0; ks < 4; ks++) {
            const int kb = ks * 8;
            unsigned int a[2][4], bf[4][2];
#pragma unroll
            for (int i = 0; i < 2; i++) {
                const unsigned int* p =
                    &As[(wm + i * 16 + (lane >> 2)) * LDA_S + kb + (lane & 3)];
                a[i][0] = p[0];
                a[i][1] = p[8 * LDA_S];
                a[i][2] = p[4];
                a[i][3] = p[8 * LDA_S + 4];
            }
#pragma unroll
            for (int j = 0; j < 4; j++) {
                const unsigned int* p =
                    &Bs[(kb + (lane & 3)) * LDB_S + wn + j * 8 + (lane >> 2)];
                bf[j][0] = p[0];
                bf[j][1] = p[4 * LDB_S];
            }
#pragma unroll
            for (int i = 0; i < 2; i++)
#pragma unroll
                for (int j = 0; j < 4; j++)
                    mma8(acc[i][j], a[i], bf[j]);
        }
    }

    // ---- epilogue ----
#pragma unroll
    for (int i = 0; i < 2; i++) {
        const int row0 = bMr + wm + i * 16 + (lane >> 2);
#pragma unroll
        for (int j = 0; j < 4; j++) {
            const int col0 = bNc + wn + j * 8 + ((lane & 3) << 1);
            float v0 = acc[i][j][0], v1 = acc[i][j][1];
            float v2 = acc[i][j][2], v3 = acc[i][j][3];
            if (EPI == 1) {
                float b0 = bias[col0], b1 = bias[col0 + 1];
                v0 += b0; v1 += b1; v2 += b0; v3 += b1;
            }
            if (EPI == 2) {
                v0 = 1.0f / (1.0f + __expf(-0.0625f * v0));
                v1 = 1.0f / (1.0f + __expf(-0.0625f * v1));
                v2 = 1.0f / (1.0f + __expf(-0.0625f * v2));
                v3 = 1.0f / (1.0f + __expf(-0.0625f * v3));
            }
            *reinterpret_cast<float2*>(Cb + (size_t)row0 * N + col0) =
                make_float2(v0, v1);
            *reinterpret_cast<float2*>(Cb + (size_t)(row0 + 8) * N + col0) =
                make_float2(v2, v3);
        }
    }
}

extern "C" void kernel_launch(void* const* d_in, const int* in_sizes, int n_in,
                              void* d_out, int out_size)
{
    (void)in_sizes; (void)n_in; (void)out_size;
    const float* q  = (const float*)d_in[0];
    const float* k  = (const float*)d_in[1];
    const float* v  = (const float*)d_in[2];
    const float* Wq = (const float*)d_in[3];
    const float* bq = (const float*)d_in[4];
    const float* Wk = (const float*)d_in[5];
    const float* bk = (const float*)d_in[6];
    const float* Wv = (const float*)d_in[7];
    const float* bv = (const float*)d_in[8];
    float* out = (float*)d_out;

    float *qp, *kp, *vp, *z;
    cudaGetSymbolAddress((void**)&qp, g_qp);
    cudaGetSymbolAddress((void**)&kp, g_kp);
    cudaGetSymbolAddress((void**)&vp, g_vp);
    cudaGetSymbolAddress((void**)&z,  g_z);

    // Projections: M = 16384, K = 1024, W is [N,K].
    gemm_tf32<0, 1><<<dim3(128,  4, 1), 256>>>(q, Wq, bq, qp,  256, 1024, 0, 0, 0);
    gemm_tf32<0, 1><<<dim3(128,  4, 1), 256>>>(k, Wk, bk, kp,  256, 1024, 0, 0, 0);
    gemm_tf32<0, 1><<<dim3(128, 16, 1), 256>>>(v, Wv, bv, vp, 1024, 1024, 0, 0, 0);

    // Scores + sigmoid: per batch M = N = 4096, K = 256; kp acts as [N,K].
    gemm_tf32<0, 2><<<dim3(32, 64, 4), 256>>>(
        qp, kp, nullptr, z, 4096, 256,
        (size_t)4096 * 256, (size_t)4096 * 256, (size_t)4096 * 4096);

    // Output: per batch M = 4096, N = 1024, K = 4096; vp is [K,N].
    gemm_tf32<1, 0><<<dim3(32, 16, 4), 256>>>(
        z, vp, nullptr, out, 1024, 4096,
        (size_t)4096 * 4096, (size_t)4096 * 1024, (size_t)4096 * 1024);
}

// round 7
// speedup vs baseline: 1.5239x; 1.5239x over previous
#include <cuda_runtime.h>

// ----------------------------------------------------------------------------
// ScaledDotProduct on GB300, round 2:
//   - prepass rounds all GEMM inputs to tf32 (rna) once
//   - GEMM: mma.sync tf32, BM=BN=128, BK=32, 8 warps (64x32 each),
//     2-stage cp.async double buffering (pure-copy staging, no cvt, no STS)
//   - sigmoid epilogue is MUFU-free (FMA/ALU only)
// ----------------------------------------------------------------------------

#define BM 128
#define BN 128
#define BK 32
#define LDA  36   // A:  [128 x 32] + 4 pad
#define LDB0 36   // B mode0: stored [n][k] = [128 x 32] + 4 pad
#define LDB1 136  // B mode1: stored [k][n] = [32 x 128] + 8 pad

// scratch (no allocations allowed)
__device__ float g_qr[(size_t)4 * 4096 * 1024];
__device__ float g_kr[(size_t)4 * 4096 * 1024];
__device__ float g_vr[(size_t)4 * 4096 * 1024];
__device__ float g_wq[(size_t)256 * 1024];
__device__ float g_wk[(size_t)256 * 1024];
__device__ float g_wv[(size_t)1024 * 1024];
__device__ float g_qp[(size_t)4 * 4096 * 256];
__device__ float g_kp[(size_t)4 * 4096 * 256];
__device__ float g_vp[(size_t)4 * 4096 * 1024];
__device__ float g_z [(size_t)4 * 4096 * 4096];

__device__ __forceinline__ unsigned int f2tf(float x) {
    unsigned int r;
    asm("cvt.rna.tf32.f32 %0, %1;" : "=r"(r) : "f"(x));
    return r;
}

__device__ __forceinline__ void cpasync16(void* dst, const void* src) {
    unsigned int d = (unsigned int)__cvta_generic_to_shared(dst);
    asm volatile("cp.async.cg.shared.global [%0], [%1], 16;" :: "r"(d), "l"(src));
}

__device__ __forceinline__ void mma8(float* c, const unsigned int* a, const unsigned int* b) {
    asm volatile(
        "mma.sync.aligned.m16n8k8.row.col.f32.tf32.tf32.f32 "
        "{%0,%1,%2,%3}, {%4,%5,%6,%7}, {%8,%9}, {%0,%1,%2,%3};\n"
        : "+f"(c[0]), "+f"(c[1]), "+f"(c[2]), "+f"(c[3])
        : "r"(a[0]), "r"(a[1]), "r"(a[2]), "r"(a[3]),
          "r"(b[0]), "r"(b[1]));
}

// sigma(x) = 1/(1 + 2^(-x*log2 e)) without any MUFU op.
__device__ __forceinline__ float sigmoid_fast(float x) {
    float t = x * -1.4426950408889634f;
    t = fminf(fmaxf(t, -30.0f), 30.0f);
    float fi = rintf(t);
    float f  = t - fi;                       // [-0.5, 0.5]
    // 2^f, Taylor deg 5 (rel err ~3e-6 on [-0.5,0.5])
    float p = 1.33335581e-3f;
    p = fmaf(p, f, 9.61812911e-3f);
    p = fmaf(p, f, 5.55041087e-2f);
    p = fmaf(p, f, 2.40226507e-1f);
    p = fmaf(p, f, 6.93147181e-1f);
    p = fmaf(p, f, 1.0f);
    int ei = (int)fi;
    float s = __int_as_float((ei + 127) << 23);   // 2^fi, fi in [-30,30]
    float d = fmaf(p, s, 1.0f);                   // 1 + 2^t
    // reciprocal: magic + 3 Newton steps
    float r = __int_as_float(0x7EF311C3 - __float_as_int(d));
    r = r * fmaf(-d, r, 2.0f);
    r = r * fmaf(-d, r, 2.0f);
    r = r * fmaf(-d, r, 2.0f);
    return r;
}

__global__ void round_tf32(const float* __restrict__ in, float* __restrict__ out, int n4) {
    int i = blockIdx.x * blockDim.x + threadIdx.x;
    if (i < n4) {
        float4 v = reinterpret_cast<const float4*>(in)[i];
        reinterpret_cast<uint4*>(out)[i] =
            make_uint4(f2tf(v.x), f2tf(v.y), f2tf(v.z), f2tf(v.w));
    }
}

// MODE_B: 0 -> B is [N,K] row-major (A @ B^T); 1 -> B is [K,N] row-major (A @ B)
// EPI:    0 -> none, 1 -> +bias then rna, 2 -> sigmoid(x/16) then rna
template <int MODE_B, int EPI>
__global__ __launch_bounds__(256, 2)
void gemm_tf32(const float* __restrict__ A, const float* __restrict__ B,
               const float* __restrict__ bias, float* __restrict__ C,
               int N, int K,
               size_t sA, size_t sB, size_t sC)
{
    extern __shared__ unsigned int sm[];
    constexpr int ASZ = BM * LDA;                                // 4608
    constexpr int BSZ = (MODE_B == 0) ? BN * LDB0 : BK * LDB1;   // 4608 / 4352
    constexpr int STW = ASZ + BSZ;

    const float* Ab = A + (size_t)blockIdx.z * sA;
    const float* Bb = B + (size_t)blockIdx.z * sB;
    float*       Cb = C + (size_t)blockIdx.z * sC;

    const int bMr  = blockIdx.x * BM;
    const int bNc  = blockIdx.y * BN;
    const int tid  = threadIdx.x;
    const int lane = tid & 31;
    const int warp = tid >> 5;
    const int wm   = (warp >> 2) * 64;   // 2 warps along M
    const int wn   = (warp & 3) * 32;    // 4 warps along N

    float acc[4][4][4];
#pragma unroll
    for (int i = 0; i < 4; i++)
#pragma unroll
        for (int j = 0; j < 4; j++)
#pragma unroll
            for (int t = 0; t < 4; t++) acc[i][j][t] = 0.0f;

    const int nch = K / BK;

    auto stage = [&](int s, int k0) {
        unsigned int* Ad = sm + s * STW;
        unsigned int* Bd = Ad + ASZ;
#pragma unroll
        for (int it = 0; it < 4; it++) {             // A: 1024 float4
            int f4 = tid + it * 256;
            int r  = f4 >> 3;
            int cc = (f4 & 7) << 2;
            cpasync16(&Ad[r * LDA + cc], Ab + (size_t)(bMr + r) * K + k0 + cc);
        }
        if (MODE_B == 0) {
#pragma unroll
            for (int it = 0; it < 4; it++) {         // B[n][k]: 1024 float4
                int f4 = tid + it * 256;
                int r  = f4 >> 3;
                int cc = (f4 & 7) << 2;
                cpasync16(&Bd[r * LDB0 + cc], Bb + (size_t)(bNc + r) * K + k0 + cc);
            }
        } else {
#pragma unroll
            for (int it = 0; it < 4; it++) {         // B[k][n]: 1024 float4
                int f4 = tid + it * 256;
                int r  = f4 >> 5;
                int cc = (f4 & 31) << 2;
                cpasync16(&Bd[r * LDB1 + cc], Bb + (size_t)(k0 + r) * N + bNc + cc);
            }
        }
        asm volatile("cp.async.commit_group;");
    };

    stage(0, 0);

    for (int c = 0; c < nch; c++) {
        if (c + 1 < nch) {
            stage((c + 1) & 1, (c + 1) * BK);
            asm volatile("cp.async.wait_group 1;");
        } else {
            asm volatile("cp.async.wait_group 0;");
        }
        __syncthreads();

        const unsigned int* Asb = sm + (c & 1) * STW;
        const unsigned int* Bsb = Asb + ASZ;

#pragma unroll
        for (int ks = 0; ks < 4; ks++) {
            const int kb = ks * 8;
            unsigned int a[4][4], bf[4][2];
#pragma unroll
            for (int i = 0; i < 4; i++) {
                const unsigned int* p =
                    &Asb[(wm + i * 16 + (lane >> 2)) * LDA + kb + (lane & 3)];
                a[i][0] = p[0];
                a[i][1] = p[8 * LDA];
                a[i][2] = p[4];
                a[i][3] = p[8 * LDA + 4];
            }
#pragma unroll
            for (int j = 0; j < 4; j++) {
                if (MODE_B == 0) {
                    const unsigned int* p =
                        &Bsb[(wn + j * 8 + (lane >> 2)) * LDB0 + kb + (lane & 3)];
                    bf[j][0] = p[0];
                    bf[j][1] = p[4];
                } else {
                    const unsigned int* p =
                        &Bsb[(kb + (lane & 3)) * LDB1 + wn + j * 8 + (lane >> 2)];
                    bf[j][0] = p[0];
                    bf[j][1] = p[4 * LDB1];
                }
            }
#pragma unroll
            for (int i = 0; i < 4; i++)
#pragma unroll
                for (int j = 0; j < 4; j++)
                    mma8(acc[i][j], a[i], bf[j]);
        }
        __syncthreads();
    }

    // ---- epilogue ----
#pragma unroll
    for (int i = 0; i < 4; i++) {
        const int row0 = bMr + wm + i * 16 + (lane >> 2);
#pragma unroll
        for (int j = 0; j < 4; j++) {
            const int col0 = bNc + wn + j * 8 + ((lane & 3) << 1);
            float v0 = acc[i][j][0], v1 = acc[i][j][1];
            float v2 = acc[i][j][2], v3 = acc[i][j][3];
            if (EPI == 1) {
                float b0 = bias[col0], b1 = bias[col0 + 1];
                v0 = __uint_as_float(f2tf(v0 + b0));
                v1 = __uint_as_float(f2tf(v1 + b1));
                v2 = __uint_as_float(f2tf(v2 + b0));
                v3 = __uint_as_float(f2tf(v3 + b1));
            }
            if (EPI == 2) {
                v0 = __uint_as_float(f2tf(sigmoid_fast(0.0625f * v0)));
                v1 = __uint_as_float(f2tf(sigmoid_fast(0.0625f * v1)));
                v2 = __uint_as_float(f2tf(sigmoid_fast(0.0625f * v2)));
                v3 = __uint_as_float(f2tf(sigmoid_fast(0.0625f * v3)));
            }
            *reinterpret_cast<float2*>(Cb + (size_t)row0 * N + col0) =
                make_float2(v0, v1);
            *reinterpret_cast<float2*>(Cb + (size_t)(row0 + 8) * N + col0) =
                make_float2(v2, v3);
        }
    }
}

extern "C" void kernel_launch(void* const* d_in, const int* in_sizes, int n_in,
                              void* d_out, int out_size)
{
    (void)in_sizes; (void)n_in; (void)out_size;
    const float* q  = (const float*)d_in[0];
    const float* k  = (const float*)d_in[1];
    const float* v  = (const float*)d_in[2];
    const float* Wq = (const float*)d_in[3];
    const float* bq = (const float*)d_in[4];
    const float* Wk = (const float*)d_in[5];
    const float* bk = (const float*)d_in[6];
    const float* Wv = (const float*)d_in[7];
    const float* bv = (const float*)d_in[8];
    float* out = (float*)d_out;

    float *qr, *kr, *vr, *wq, *wk, *wv, *qp, *kp, *vp, *z;
    cudaGetSymbolAddress((void**)&qr, g_qr);
    cudaGetSymbolAddress((void**)&kr, g_kr);
    cudaGetSymbolAddress((void**)&vr, g_vr);
    cudaGetSymbolAddress((void**)&wq, g_wq);
    cudaGetSymbolAddress((void**)&wk, g_wk);
    cudaGetSymbolAddress((void**)&wv, g_wv);
    cudaGetSymbolAddress((void**)&qp, g_qp);
    cudaGetSymbolAddress((void**)&kp, g_kp);
    cudaGetSymbolAddress((void**)&vp, g_vp);
    cudaGetSymbolAddress((void**)&z,  g_z);

    const size_t SM0 = 2 * (size_t)(BM * LDA + BN * LDB0) * 4;  // 73728
    const size_t SM1 = 2 * (size_t)(BM * LDA + BK * LDB1) * 4;  // 71680
    cudaFuncSetAttribute(gemm_tf32<0, 1>, cudaFuncAttributeMaxDynamicSharedMemorySize, (int)SM0);
    cudaFuncSetAttribute(gemm_tf32<0, 2>, cudaFuncAttributeMaxDynamicSharedMemorySize, (int)SM0);
    cudaFuncSetAttribute(gemm_tf32<1, 0>, cudaFuncAttributeMaxDynamicSharedMemorySize, (int)SM1);

    // prepass: tf32-round all GEMM inputs
    const int n4_qkv = (4 * 4096 * 1024) / 4;     // 4.19M float4
    const int n4_wqk = (256 * 1024) / 4;
    const int n4_wv  = (1024 * 1024) / 4;
    round_tf32<<<(n4_qkv + 255) / 256, 256>>>(q,  qr, n4_qkv);
    round_tf32<<<(n4_qkv + 255) / 256, 256>>>(k,  kr, n4_qkv);
    round_tf32<<<(n4_qkv + 255) / 256, 256>>>(v,  vr, n4_qkv);
    round_tf32<<<(n4_wqk + 255) / 256, 256>>>(Wq, wq, n4_wqk);
    round_tf32<<<(n4_wqk + 255) / 256, 256>>>(Wk, wk, n4_wqk);
    round_tf32<<<(n4_wv  + 255) / 256, 256>>>(Wv, wv, n4_wv);

    // Projections: M = 16384, K = 1024, W is [N,K].
    gemm_tf32<0, 1><<<dim3(128, 2, 1), 256, SM0>>>(qr, wq, bq, qp,  256, 1024, 0, 0, 0);
    gemm_tf32<0, 1><<<dim3(128, 2, 1), 256, SM0>>>(kr, wk, bk, kp,  256, 1024, 0, 0, 0);
    gemm_tf32<0, 1><<<dim3(128, 8, 1), 256, SM0>>>(vr, wv, bv, vp, 1024, 1024, 0, 0, 0);

    // Scores + sigmoid: per batch M = N = 4096, K = 256.
    gemm_tf32<0, 2><<<dim3(32, 32, 4), 256, SM0>>>(
        qp, kp, nullptr, z, 4096, 256,
        (size_t)4096 * 256, (size_t)4096 * 256, (size_t)4096 * 4096);

    // Output: per batch M = 4096, N = 1024, K = 4096; vp is [K,N].
    gemm_tf32<1, 0><<<dim3(32, 8, 4), 256, SM1>>>(
        z, vp, nullptr, out, 1024, 4096,
        (size_t)4096 * 4096, (size_t)4096 * 1024, (size_t)4096 * 1024);
}

// round 8
// speedup vs baseline: 2.3360x; 1.5329x over previous
#include <cuda_runtime.h>
#include <cuda_fp16.h>

// ----------------------------------------------------------------------------
// ScaledDotProduct on GB300, round 7: full fp16 pipeline (fp32 accumulate).
//   - prepass converts q/k/v/W fp32 -> fp16 once (same mantissa as tf32)
//   - GEMM: mma.sync m16n8k16 f16, BM=BN=128, BK=32, 8 warps (64x32 each),
//     2-stage cp.async double buffering, pure-copy staging
//   - intermediates qp/kp/vp/z stored fp16 (halves DRAM + smem traffic)
//   - sigmoid epilogue MUFU-free
// ----------------------------------------------------------------------------

#define BM 128
#define BN 128
#define BK 32
#define LDAh  40   // halves: BK + 8 pad (80B row -> 16B aligned, LDS conflict-free)
#define LDB0h 40   // B mode0 stored [n][k]
#define LDB1h 136  // B mode1 stored [k][n]: BN + 8 pad (272B row)

// scratch (__device__ globals; 16B-aligned for cp.async / vector ops)
__device__ __align__(256) __half g_qh[(size_t)4 * 4096 * 1024];
__device__ __align__(256) __half g_kh[(size_t)4 * 4096 * 1024];
__device__ __align__(256) __half g_vh[(size_t)4 * 4096 * 1024];
__device__ __align__(256) __half g_wq[(size_t)256 * 1024];
__device__ __align__(256) __half g_wk[(size_t)256 * 1024];
__device__ __align__(256) __half g_wv[(size_t)1024 * 1024];
__device__ __align__(256) __half g_qp[(size_t)4 * 4096 * 256];
__device__ __align__(256) __half g_kp[(size_t)4 * 4096 * 256];
__device__ __align__(256) __half g_vp[(size_t)4 * 4096 * 1024];
__device__ __align__(256) __half g_z [(size_t)4 * 4096 * 4096];

__device__ __forceinline__ void cpasync16(void* dst, const void* src) {
    unsigned int d = (unsigned int)__cvta_generic_to_shared(dst);
    asm volatile("cp.async.cg.shared.global [%0], [%1], 16;" :: "r"(d), "l"(src));
}

__device__ __forceinline__ void mma16(float* c, const unsigned int* a, const unsigned int* b) {
    asm volatile(
        "mma.sync.aligned.m16n8k16.row.col.f32.f16.f16.f32 "
        "{%0,%1,%2,%3}, {%4,%5,%6,%7}, {%8,%9}, {%0,%1,%2,%3};\n"
        : "+f"(c[0]), "+f"(c[1]), "+f"(c[2]), "+f"(c[3])
        : "r"(a[0]), "r"(a[1]), "r"(a[2]), "r"(a[3]),
          "r"(b[0]), "r"(b[1]));
}

// sigma(x) = 1/(1 + 2^(-x*log2 e)) without any MUFU op.
__device__ __forceinline__ float sigmoid_fast(float x) {
    float t = x * -1.4426950408889634f;
    t = fminf(fmaxf(t, -30.0f), 30.0f);
    float fi = rintf(t);
    float f  = t - fi;                       // [-0.5, 0.5]
    float p = 1.33335581e-3f;
    p = fmaf(p, f, 9.61812911e-3f);
    p = fmaf(p, f, 5.55041087e-2f);
    p = fmaf(p, f, 2.40226507e-1f);
    p = fmaf(p, f, 6.93147181e-1f);
    p = fmaf(p, f, 1.0f);
    int ei = (int)fi;
    float s = __int_as_float((ei + 127) << 23);   // 2^fi
    float d = fmaf(p, s, 1.0f);                   // 1 + 2^t
    float r = __int_as_float(0x7EF311C3 - __float_as_int(d));
    r = r * fmaf(-d, r, 2.0f);
    r = r * fmaf(-d, r, 2.0f);
    r = r * fmaf(-d, r, 2.0f);
    return r;
}

__global__ void to_half(const float* __restrict__ in, __half* __restrict__ out, int n4) {
    int i = blockIdx.x * blockDim.x + threadIdx.x;
    if (i < n4) {
        float4 v = reinterpret_cast<const float4*>(in)[i];
        __half2 h0 = __floats2half2_rn(v.x, v.y);
        __half2 h1 = __floats2half2_rn(v.z, v.w);
        reinterpret_cast<uint2*>(out)[i] =
            make_uint2(*reinterpret_cast<unsigned int*>(&h0),
                       *reinterpret_cast<unsigned int*>(&h1));
    }
}

// MODE_B: 0 -> B is [N,K] half row-major (A @ B^T); 1 -> B is [K,N] half (A @ B)
// EPI:    0 -> fp32 store, 1 -> +bias then half store, 2 -> sigmoid(x/16) half store
template <int MODE_B, int EPI>
__global__ __launch_bounds__(256, 2)
void gemm_f16(const __half* __restrict__ A, const __half* __restrict__ B,
              const float* __restrict__ bias, void* __restrict__ Cv,
              int N, int K,
              size_t sA, size_t sB, size_t sC)
{
    extern __shared__ __half sm[];
    constexpr int ASZ = BM * LDAh;                                 // 5120 halves
    constexpr int BSZ = (MODE_B == 0) ? BN * LDB0h : BK * LDB1h;   // 5120 / 4352
    constexpr int STW = ASZ + BSZ;

    const __half* Ab = A + (size_t)blockIdx.z * sA;
    const __half* Bb = B + (size_t)blockIdx.z * sB;

    const int bMr  = blockIdx.x * BM;
    const int bNc  = blockIdx.y * BN;
    const int tid  = threadIdx.x;
    const int lane = tid & 31;
    const int warp = tid >> 5;
    const int wm   = (warp >> 2) * 64;   // 2 warps along M
    const int wn   = (warp & 3) * 32;    // 4 warps along N

    float acc[4][4][4];
#pragma unroll
    for (int i = 0; i < 4; i++)
#pragma unroll
        for (int j = 0; j < 4; j++)
#pragma unroll
            for (int t = 0; t < 4; t++) acc[i][j][t] = 0.0f;

    const int nch = K / BK;

    auto stage = [&](int s, int k0) {
        __half* Ad = sm + s * STW;
        __half* Bd = Ad + ASZ;
        // A tile: BM x BK halves = 512 x 16B ; 4 x 16B per row
#pragma unroll
        for (int it = 0; it < 2; it++) {
            int f4 = tid + it * 256;
            int r  = f4 >> 2;
            int cc = (f4 & 3) << 3;   // halves
            cpasync16(&Ad[r * LDAh + cc], Ab + (size_t)(bMr + r) * K + k0 + cc);
        }
        if (MODE_B == 0) {
            // B[n][k]: BN x BK halves = 512 x 16B
#pragma unroll
            for (int it = 0; it < 2; it++) {
                int f4 = tid + it * 256;
                int r  = f4 >> 2;
                int cc = (f4 & 3) << 3;
                cpasync16(&Bd[r * LDB0h + cc], Bb + (size_t)(bNc + r) * K + k0 + cc);
            }
        } else {
            // B[k][n]: BK x BN halves = 512 x 16B ; 16 x 16B per row
#pragma unroll
            for (int it = 0; it < 2; it++) {
                int f4 = tid + it * 256;
                int r  = f4 >> 4;
                int cc = (f4 & 15) << 3;
                cpasync16(&Bd[r * LDB1h + cc], Bb + (size_t)(k0 + r) * N + bNc + cc);
            }
        }
        asm volatile("cp.async.commit_group;");
    };

    stage(0, 0);

    for (int c = 0; c < nch; c++) {
        if (c + 1 < nch) {
            stage((c + 1) & 1, (c + 1) * BK);
            asm volatile("cp.async.wait_group 1;");
        } else {
            asm volatile("cp.async.wait_group 0;");
        }
        __syncthreads();

        const __half* Asb = sm + (c & 1) * STW;
        const __half* Bsb = Asb + ASZ;

#pragma unroll
        for (int ks = 0; ks < 2; ks++) {            // two k16 steps per BK=32
            const int kb = ks * 16;                 // halves
            unsigned int a[4][4], bf[4][2];
#pragma unroll
            for (int i = 0; i < 4; i++) {
                const int row = wm + i * 16 + (lane >> 2);
                const unsigned int* p = reinterpret_cast<const unsigned int*>(
                    &Asb[row * LDAh + kb]) + (lane & 3);
                a[i][0] = p[0];
                a[i][1] = p[(8 * LDAh) >> 1];
                a[i][2] = p[4];
                a[i][3] = p[((8 * LDAh) >> 1) + 4];
            }
#pragma unroll
            for (int j = 0; j < 4; j++) {
                if (MODE_B == 0) {
                    const int n = wn + j * 8 + (lane >> 2);
                    const unsigned int* p = reinterpret_cast<const unsigned int*>(
                        &Bsb[n * LDB0h + kb]) + (lane & 3);
                    bf[j][0] = p[0];
                    bf[j][1] = p[4];
                } else {
                    const int n = wn + j * 8 + (lane >> 2);
                    const int kk = kb + ((lane & 3) << 1);
                    const unsigned short* ps = reinterpret_cast<const unsigned short*>(
                        &Bsb[kk * LDB1h + n]);
                    bf[j][0] = (unsigned int)ps[0] |
                               ((unsigned int)ps[LDB1h] << 16);
                    bf[j][1] = (unsigned int)ps[8 * LDB1h] |
                               ((unsigned int)ps[9 * LDB1h] << 16);
                }
            }
#pragma unroll
            for (int i = 0; i < 4; i++)
#pragma unroll
                for (int j = 0; j < 4; j++)
                    mma16(acc[i][j], a[i], bf[j]);
        }
        __syncthreads();
    }

    // ---- epilogue ----
#pragma unroll
    for (int i = 0; i < 4; i++) {
        const int row0 = bMr + wm + i * 16 + (lane >> 2);
#pragma unroll
        for (int j = 0; j < 4; j++) {
            const int col0 = bNc + wn + j * 8 + ((lane & 3) << 1);
            float v0 = acc[i][j][0], v1 = acc[i][j][1];
            float v2 = acc[i][j][2], v3 = acc[i][j][3];
            if (EPI == 0) {
                float* Cb = (float*)Cv + (size_t)blockIdx.z * sC;
                *reinterpret_cast<float2*>(Cb + (size_t)row0 * N + col0) =
                    make_float2(v0, v1);
                *reinterpret_cast<float2*>(Cb + (size_t)(row0 + 8) * N + col0) =
                    make_float2(v2, v3);
            } else {
                if (EPI == 1) {
                    float b0 = bias[col0], b1 = bias[col0 + 1];
                    v0 += b0; v1 += b1; v2 += b0; v3 += b1;
                }
                if (EPI == 2) {
                    v0 = sigmoid_fast(0.0625f * v0);
                    v1 = sigmoid_fast(0.0625f * v1);
                    v2 = sigmoid_fast(0.0625f * v2);
                    v3 = sigmoid_fast(0.0625f * v3);
                }
                __half* Cb = (__half*)Cv + (size_t)blockIdx.z * sC;
                *reinterpret_cast<__half2*>(Cb + (size_t)row0 * N + col0) =
                    __floats2half2_rn(v0, v1);
                *reinterpret_cast<__half2*>(Cb + (size_t)(row0 + 8) * N + col0) =
                    __floats2half2_rn(v2, v3);
            }
        }
    }
}

extern "C" void kernel_launch(void* const* d_in, const int* in_sizes, int n_in,
                              void* d_out, int out_size)
{
    (void)in_sizes; (void)n_in; (void)out_size;
    const float* q  = (const float*)d_in[0];
    const float* k  = (const float*)d_in[1];
    const float* v  = (const float*)d_in[2];
    const float* Wq = (const float*)d_in[3];
    const float* bq = (const float*)d_in[4];
    const float* Wk = (const float*)d_in[5];
    const float* bk = (const float*)d_in[6];
    const float* Wv = (const float*)d_in[7];
    const float* bv = (const float*)d_in[8];
    float* out = (float*)d_out;

    __half *qh, *kh, *vh, *wq, *wk, *wv, *qp, *kp, *vp, *z;
    cudaGetSymbolAddress((void**)&qh, g_qh);
    cudaGetSymbolAddress((void**)&kh, g_kh);
    cudaGetSymbolAddress((void**)&vh, g_vh);
    cudaGetSymbolAddress((void**)&wq, g_wq);
    cudaGetSymbolAddress((void**)&wk, g_wk);
    cudaGetSymbolAddress((void**)&wv, g_wv);
    cudaGetSymbolAddress((void**)&qp, g_qp);
    cudaGetSymbolAddress((void**)&kp, g_kp);
    cudaGetSymbolAddress((void**)&vp, g_vp);
    cudaGetSymbolAddress((void**)&z,  g_z);

    const size_t SM0 = 2 * (size_t)(BM * LDAh + BN * LDB0h) * 2;  // 40960 B
    const size_t SM1 = 2 * (size_t)(BM * LDAh + BK * LDB1h) * 2;  // 37888 B
    cudaFuncSetAttribute(gemm_f16<0, 1>, cudaFuncAttributeMaxDynamicSharedMemorySize, (int)SM0);
    cudaFuncSetAttribute(gemm_f16<0, 2>, cudaFuncAttributeMaxDynamicSharedMemorySize, (int)SM0);
    cudaFuncSetAttribute(gemm_f16<1, 0>, cudaFuncAttributeMaxDynamicSharedMemorySize, (int)SM1);

    // prepass: fp32 -> fp16
    const int n4_qkv = (4 * 4096 * 1024) / 4;
    const int n4_wqk = (256 * 1024) / 4;
    const int n4_wv  = (1024 * 1024) / 4;
    to_half<<<(n4_qkv + 255) / 256, 256>>>(q,  qh, n4_qkv);
    to_half<<<(n4_qkv + 255) / 256, 256>>>(k,  kh, n4_qkv);
    to_half<<<(n4_qkv + 255) / 256, 256>>>(v,  vh, n4_qkv);
    to_half<<<(n4_wqk + 255) / 256, 256>>>(Wq, wq, n4_wqk);
    to_half<<<(n4_wqk + 255) / 256, 256>>>(Wk, wk, n4_wqk);
    to_half<<<(n4_wv  + 255) / 256, 256>>>(Wv, wv, n4_wv);

    // Projections: M = 16384, K = 1024, W is [N,K].
    gemm_f16<0, 1><<<dim3(128, 2, 1), 256, SM0>>>(qh, wq, bq, qp,  256, 1024, 0, 0, 0);
    gemm_f16<0, 1><<<dim3(128, 2, 1), 256, SM0>>>(kh, wk, bk, kp,  256, 1024, 0, 0, 0);
    gemm_f16<0, 1><<<dim3(128, 8, 1), 256, SM0>>>(vh, wv, bv, vp, 1024, 1024, 0, 0, 0);

    // Scores + sigmoid: per batch M = N = 4096, K = 256.
    gemm_f16<0, 2><<<dim3(32, 32, 4), 256, SM0>>>(
        qp, kp, nullptr, z, 4096, 256,
        (size_t)4096 * 256, (size_t)4096 * 256, (size_t)4096 * 4096);

    // Output: per batch M = 4096, N = 1024, K = 4096; vp is [K,N].
    gemm_f16<1, 0><<<dim3(32, 8, 4), 256, SM1>>>(
        z, vp, nullptr, out, 1024, 4096,
        (size_t)4096 * 4096, (size_t)4096 * 1024, (size_t)4096 * 1024);
}